// round 2
// baseline (speedup 1.0000x reference)
#include <cuda_runtime.h>
#include <cuda_bf16.h>
#include <cstdint>

// ---------------------------------------------------------------------------
// HybridCodebook forward:
//   frozen  = normalize(semantic_embeddings)   [8192,1024]
//   learned = normalize(learnable_entries)     [128,1024]
//   codebook = concat(frozen, learned)         [8320,1024]
//   xn = normalize(x)                          [8192,1024]
//   logits = xn @ codebook^T                   [8192,8320]
//   indices = argmax(logits, -1); z_q = codebook[indices]; z_q_st == z_q (fwd)
//   commitment = mean(1 - cos(xn, z_q)); vq = sum over learnable hits / count
// Output layout (float32, concat of flattened outputs in return order):
//   [logits | indices | z_q | z_q_st | vq | commit | quant]
// ---------------------------------------------------------------------------

#define NTOK   8192
#define DIM    1024
#define NSEM   8192
#define NLRN   128
#define NCB    (NSEM + NLRN)          // 8320

static const size_t OFF_LOGITS = 0;
static const size_t OFF_IDX    = (size_t)NTOK * NCB;              // 68,157,440
static const size_t OFF_ZQ     = OFF_IDX + NTOK;                  // +8192
static const size_t OFF_ZQST   = OFF_ZQ + (size_t)NTOK * DIM;
static const size_t OFF_SC     = OFF_ZQST + (size_t)NTOK * DIM;   // 3 scalars

// ---- scratch (device globals: no allocations allowed) ----
__device__ float g_xn[(size_t)NTOK * DIM];      // normalized x
__device__ float g_cb[(size_t)NCB * DIM];       // normalized codebook
__device__ unsigned long long g_best[NTOK];     // packed (monofloat<<32)|(~col)
__device__ double g_commit_sum;
__device__ double g_vq_sum;
__device__ int    g_vq_cnt;

// monotone float<->uint mapping (all logits finite, in [-1,1])
__device__ __forceinline__ unsigned f2mono(float f) {
    unsigned u = __float_as_uint(f);
    return (u & 0x80000000u) ? ~u : (u | 0x80000000u);
}
__device__ __forceinline__ float mono2f(unsigned m) {
    return (m & 0x80000000u) ? __uint_as_float(m ^ 0x80000000u)
                             : __uint_as_float(~m);
}

// ---------------------------------------------------------------------------
__global__ void init_state() {
    int i = blockIdx.x * blockDim.x + threadIdx.x;
    if (i < NTOK) g_best[i] = 0ull;
    if (i == 0) { g_commit_sum = 0.0; g_vq_sum = 0.0; g_vq_cnt = 0; }
}

// one block (256 threads) per row; D=1024 => one float4 per thread
__global__ void normalize_rows(const float* __restrict__ in,
                               float* __restrict__ out) {
    const int row = blockIdx.x;
    const int tid = threadIdx.x;
    const float4* src = (const float4*)(in + (size_t)row * DIM);
    float4 v = src[tid];
    float s = v.x * v.x + v.y * v.y + v.z * v.z + v.w * v.w;
    // warp reduce
    #pragma unroll
    for (int off = 16; off; off >>= 1) s += __shfl_xor_sync(0xFFFFFFFFu, s, off);
    __shared__ float red[8];
    if ((tid & 31) == 0) red[tid >> 5] = s;
    __syncthreads();
    __shared__ float s_inv;
    if (tid == 0) {
        float t = red[0] + red[1] + red[2] + red[3] +
                  red[4] + red[5] + red[6] + red[7];
        s_inv = 1.0f / fmaxf(sqrtf(t), 1e-8f);
    }
    __syncthreads();
    float inv = s_inv;
    float4 o = make_float4(v.x * inv, v.y * inv, v.z * inv, v.w * inv);
    ((float4*)(out + (size_t)row * DIM))[tid] = o;
}

// ---------------------------------------------------------------------------
// SGEMM (NT): C[i,j] = dot(A_row_i, B_row_j), fused per-row max/argmax.
// BM=BN=128, BK=16, 256 threads, 8x8 per thread.
__global__ void __launch_bounds__(256, 2)
gemm_rowmax(const float* __restrict__ A, const float* __restrict__ B,
            float* __restrict__ C, unsigned long long* __restrict__ best) {
    __shared__ float As[16][128];
    __shared__ float Bs[16][128];
    const int tid = threadIdx.x;
    const int tx = tid & 15;           // col group
    const int ty = tid >> 4;           // row group
    const int rowBase = blockIdx.y * 128;
    const int colBase = blockIdx.x * 128;

    float acc[8][8];
    #pragma unroll
    for (int i = 0; i < 8; ++i)
        #pragma unroll
        for (int j = 0; j < 8; ++j) acc[i][j] = 0.0f;

    const int r0  = tid >> 2;          // 0..63
    const int kk0 = (tid & 3) << 2;    // 0,4,8,12

    for (int k0 = 0; k0 < DIM; k0 += 16) {
        #pragma unroll
        for (int l = 0; l < 2; ++l) {
            int r = r0 + l * 64;
            float4 av = *(const float4*)&A[(size_t)(rowBase + r) * DIM + k0 + kk0];
            As[kk0 + 0][r] = av.x; As[kk0 + 1][r] = av.y;
            As[kk0 + 2][r] = av.z; As[kk0 + 3][r] = av.w;
            float4 bv = *(const float4*)&B[(size_t)(colBase + r) * DIM + k0 + kk0];
            Bs[kk0 + 0][r] = bv.x; Bs[kk0 + 1][r] = bv.y;
            Bs[kk0 + 2][r] = bv.z; Bs[kk0 + 3][r] = bv.w;
        }
        __syncthreads();
        #pragma unroll
        for (int k = 0; k < 16; ++k) {
            float a[8], b[8];
            *(float4*)&a[0] = *(const float4*)&As[k][ty * 8];
            *(float4*)&a[4] = *(const float4*)&As[k][ty * 8 + 4];
            *(float4*)&b[0] = *(const float4*)&Bs[k][tx * 8];
            *(float4*)&b[4] = *(const float4*)&Bs[k][tx * 8 + 4];
            #pragma unroll
            for (int i = 0; i < 8; ++i)
                #pragma unroll
                for (int j = 0; j < 8; ++j)
                    acc[i][j] = fmaf(a[i], b[j], acc[i][j]);
        }
        __syncthreads();
    }

    // epilogue: store logits tile + per-row (max, argmax) merge
    #pragma unroll
    for (int i = 0; i < 8; ++i) {
        int row = rowBase + ty * 8 + i;
        float* crow = C + (size_t)row * NCB + colBase + tx * 8;
        *(float4*)crow       = make_float4(acc[i][0], acc[i][1], acc[i][2], acc[i][3]);
        *(float4*)(crow + 4) = make_float4(acc[i][4], acc[i][5], acc[i][6], acc[i][7]);

        float m = acc[i][0]; int mj = 0;
        #pragma unroll
        for (int j = 1; j < 8; ++j)
            if (acc[i][j] > m) { m = acc[i][j]; mj = j; }  // strict > : first max wins
        unsigned col = (unsigned)(colBase + tx * 8 + mj);
        unsigned long long pk =
            ((unsigned long long)f2mono(m) << 32) | (0xFFFFFFFFu - col);
        // reduce across the 16 lanes sharing this row (lanes [0,16) / [16,32))
        #pragma unroll
        for (int off = 8; off; off >>= 1) {
            unsigned long long o = __shfl_xor_sync(0xFFFFFFFFu, pk, off, 16);
            pk = (o > pk) ? o : pk;
        }
        if (tx == 0) atomicMax(&best[row], pk);
    }
}

// ---------------------------------------------------------------------------
// gather z_q / z_q_st, write index, accumulate losses
__global__ void gather_losses(float* __restrict__ out) {
    const int row = blockIdx.x;
    const int tid = threadIdx.x;
    unsigned long long p = g_best[row];
    unsigned idx = 0xFFFFFFFFu - (unsigned)(p & 0xFFFFFFFFull);

    const float4* src  = (const float4*)(g_cb + (size_t)idx * DIM);
    float4* zq   = (float4*)(out + OFF_ZQ   + (size_t)row * DIM);
    float4* zqst = (float4*)(out + OFF_ZQST + (size_t)row * DIM);
    float4 v = src[tid];
    zq[tid]   = v;
    zqst[tid] = v;

    if (tid == 0) {
        out[OFF_IDX + row] = (float)idx;
        float ml = mono2f((unsigned)(p >> 32));
        double l = 1.0 - (double)ml;      // 1 - cos(xn, z_q) (unit vectors)
        atomicAdd(&g_commit_sum, l);
        if (idx >= (unsigned)NSEM) {
            atomicAdd(&g_vq_sum, l);
            atomicAdd(&g_vq_cnt, 1);
        }
    }
}

__global__ void finalize(float* __restrict__ out) {
    double commit = g_commit_sum / (double)NTOK;
    double vq     = g_vq_sum / ((double)g_vq_cnt + 1e-6);
    out[OFF_SC + 0] = (float)vq;
    out[OFF_SC + 1] = (float)commit;
    out[OFF_SC + 2] = (float)(vq + 0.25 * commit);
}

// ---------------------------------------------------------------------------
extern "C" void kernel_launch(void* const* d_in, const int* in_sizes, int n_in,
                              void* d_out, int out_size) {
    const float* x    = (const float*)d_in[0];  // [8192,1024]
    const float* sem  = (const float*)d_in[1];  // [8192,1024]
    const float* lrn  = (const float*)d_in[2];  // [128,1024]
    float* out = (float*)d_out;

    float* xn; cudaGetSymbolAddress((void**)&xn, g_xn);
    float* cb; cudaGetSymbolAddress((void**)&cb, g_cb);
    unsigned long long* best; cudaGetSymbolAddress((void**)&best, g_best);

    init_state<<<32, 256>>>();
    normalize_rows<<<NTOK, 256>>>(x, xn);
    normalize_rows<<<NSEM, 256>>>(sem, cb);
    normalize_rows<<<NLRN, 256>>>(lrn, cb + (size_t)NSEM * DIM);

    dim3 grid(NCB / 128, NTOK / 128);   // (65, 64)
    gemm_rowmax<<<grid, 256>>>(xn, cb, out + OFF_LOGITS, best);

    gather_losses<<<NTOK, 256>>>(out);
    finalize<<<1, 1>>>(out);
}

// round 11
// speedup vs baseline: 1.8771x; 1.8771x over previous
#include <cuda_runtime.h>
#include <cuda_bf16.h>
#include <cstdint>

// ---------------------------------------------------------------------------
// HybridCodebook forward — bf16-split HMMA (family-portable; tcgen05 is not
// available at the harness's compute_103 PTX target).
//  logits  : one K=3072 bf16 GEMM computing hi*hi + lo*hi + hi*lo
//            (3-term compensated product; rel err ~1e-5 << 1e-3 threshold)
//  indices : approx rowmax in GEMM epilogue + exact fp32 candidate refinement
//  z_q etc : exact fp32
// Output layout (f32): [logits | indices | z_q | z_q_st | vq | commit | quant]
// ---------------------------------------------------------------------------

#define NTOK   8192
#define DIM    1024
#define KDIM   3072              // [hi | lo | hi] x [hi | hi | lo]
#define NSEM   8192
#define NLRN   128
#define NCB    (NSEM + NLRN)     // 8320 = 65 * 128

#define BM     128
#define BN     128
#define BK     32
#define NITER  (KDIM / BK)       // 96
#define PITCH  40                // halves per smem row (32 + 8 pad) = 80 B
#define DELTA  1e-3f             // argmax candidate margin

static const size_t OFF_LOGITS = 0;
static const size_t OFF_IDX    = (size_t)NTOK * NCB;
static const size_t OFF_ZQ     = OFF_IDX + NTOK;
static const size_t OFF_ZQST   = OFF_ZQ + (size_t)NTOK * DIM;
static const size_t OFF_SC     = OFF_ZQST + (size_t)NTOK * DIM;

// ---- device-global scratch (no allocations allowed) ----
__device__ float          g_xn[(size_t)NTOK * DIM];
__device__ float          g_cb[(size_t)NCB * DIM];
__device__ __nv_bfloat16  g_xh2[(size_t)NTOK * KDIM];   // [hi | lo | hi]
__device__ __nv_bfloat16  g_ch2[(size_t)NCB * KDIM];    // [hi | hi | lo]
__device__ unsigned long long g_best[NTOK];             // (monofloat<<32) | (~col)
__device__ double g_commit_sum;
__device__ double g_vq_sum;
__device__ int    g_vq_cnt;

// ---------------------------------------------------------------------------
__device__ __forceinline__ uint32_t smem_u32(const void* p) {
    uint32_t a;
    asm("{ .reg .u64 t; cvta.to.shared.u64 t, %1; cvt.u32.u64 %0, t; }"
        : "=r"(a) : "l"(p));
    return a;
}
#define CP_ASYNC16(dst, src) \
    asm volatile("cp.async.cg.shared.global [%0], [%1], 16;" :: "r"(dst), "l"(src))
#define CP_COMMIT() asm volatile("cp.async.commit_group;" ::: "memory")
#define CP_WAIT1()  asm volatile("cp.async.wait_group 1;" ::: "memory")
#define CP_WAIT0()  asm volatile("cp.async.wait_group 0;" ::: "memory")
#define LDSM_X4(R0, R1, R2, R3, ADDR) \
    asm volatile("ldmatrix.sync.aligned.m8n8.x4.shared.b16 {%0,%1,%2,%3}, [%4];" \
                 : "=r"(R0), "=r"(R1), "=r"(R2), "=r"(R3) : "r"(ADDR))
#define MMA16816(D, A, B) \
    asm volatile("mma.sync.aligned.m16n8k16.row.col.f32.bf16.bf16.f32 " \
                 "{%0,%1,%2,%3}, {%4,%5,%6,%7}, {%8,%9}, {%0,%1,%2,%3};" \
                 : "+f"((D)[0]), "+f"((D)[1]), "+f"((D)[2]), "+f"((D)[3]) \
                 : "r"((A)[0]), "r"((A)[1]), "r"((A)[2]), "r"((A)[3]), \
                   "r"((B)[0]), "r"((B)[1]))

__device__ __forceinline__ unsigned f2mono(float f) {
    unsigned u = __float_as_uint(f);
    return (u & 0x80000000u) ? ~u : (u | 0x80000000u);
}
__device__ __forceinline__ float mono2f(unsigned m) {
    return (m & 0x80000000u) ? __uint_as_float(m ^ 0x80000000u) : __uint_as_float(~m);
}
__device__ __forceinline__ unsigned long long packmax(float v, int col) {
    return ((unsigned long long)f2mono(v) << 32) | (0xFFFFFFFFu - (unsigned)col);
}

// ---------------------------------------------------------------------------
__global__ void init_state() {
    int i = blockIdx.x * blockDim.x + threadIdx.x;
    if (i < NTOK) g_best[i] = 0ull;
    if (i == 0) { g_commit_sum = 0.0; g_vq_sum = 0.0; g_vq_cnt = 0; }
}

// one block (256 threads) per row; fp32 out + bf16 hi/lo split out.
// hi is written at offsets offH1 and offH2, lo at offL (within the KDIM row).
__global__ void normalize_rows(const float* __restrict__ in,
                               float* __restrict__ outf,
                               __nv_bfloat16* __restrict__ outh,
                               int offH1, int offH2, int offL) {
    const int row = blockIdx.x;
    const int tid = threadIdx.x;
    float4 v = ((const float4*)(in + (size_t)row * DIM))[tid];
    float s = v.x * v.x + v.y * v.y + v.z * v.z + v.w * v.w;
    #pragma unroll
    for (int off = 16; off; off >>= 1) s += __shfl_xor_sync(0xFFFFFFFFu, s, off);
    __shared__ float red[8];
    if ((tid & 31) == 0) red[tid >> 5] = s;
    __syncthreads();
    __shared__ float s_inv;
    if (tid == 0) {
        float t = red[0] + red[1] + red[2] + red[3] + red[4] + red[5] + red[6] + red[7];
        s_inv = 1.0f / fmaxf(sqrtf(t), 1e-8f);
    }
    __syncthreads();
    float inv = s_inv;
    float o[4] = {v.x * inv, v.y * inv, v.z * inv, v.w * inv};
    ((float4*)(outf + (size_t)row * DIM))[tid] = make_float4(o[0], o[1], o[2], o[3]);

    __nv_bfloat16 hi[4], lo[4];
    #pragma unroll
    for (int q = 0; q < 4; ++q) {
        hi[q] = __float2bfloat16(o[q]);
        lo[q] = __float2bfloat16(o[q] - __bfloat162float(hi[q]));
    }
    __nv_bfloat16* rowp = outh + (size_t)row * KDIM;
    *(uint2*)(rowp + offH1 + tid * 4) = *(uint2*)hi;
    *(uint2*)(rowp + offH2 + tid * 4) = *(uint2*)hi;
    *(uint2*)(rowp + offL  + tid * 4) = *(uint2*)lo;
}

// ---------------------------------------------------------------------------
// bf16 GEMM: C[8192, 8320] = xh2 @ ch2^T over K=3072, fused per-row rowmax.
// 256 thr = 8 warps (2 M x 4 N), warp tile 64x32, mma m16n8k16, cp.async x2 buf.
// ---------------------------------------------------------------------------
__global__ void __launch_bounds__(256)
gemm_mma(const __nv_bfloat16* __restrict__ Ah, const __nv_bfloat16* __restrict__ Bh,
         float* __restrict__ C, unsigned long long* __restrict__ best) {
    __shared__ __align__(16) __nv_bfloat16 As[2][BM * PITCH];
    __shared__ __align__(16) __nv_bfloat16 Bs[2][BM * PITCH];

    const int tid  = threadIdx.x;
    const int lane = tid & 31;
    const int wid  = tid >> 5;
    const int wy   = wid >> 2;          // 0..1  (M)
    const int wx   = wid & 3;           // 0..3  (N)
    const int rowBase = blockIdx.y * BM;
    const int colBase = blockIdx.x * BN;

    // cp.async assignments: 512 16B-chunks per tile, 2 per thread
    const int c0r = tid >> 2, c0k = tid & 3;
    const int c1r = (tid + 256) >> 2, c1k = c0k;

    const uint32_t aBase0 = smem_u32(As[0]), aBase1 = smem_u32(As[1]);
    const uint32_t bBase0 = smem_u32(Bs[0]), bBase1 = smem_u32(Bs[1]);

    float acc[4][4][4];
    #pragma unroll
    for (int mi = 0; mi < 4; ++mi)
        #pragma unroll
        for (int ni = 0; ni < 4; ++ni)
            #pragma unroll
            for (int q = 0; q < 4; ++q) acc[mi][ni][q] = 0.0f;

    auto load_tile = [&](int buf, int ki) {
        uint32_t ab = buf ? aBase1 : aBase0;
        uint32_t bb = buf ? bBase1 : bBase0;
        const __nv_bfloat16* gA = Ah + (size_t)(rowBase + c0r) * KDIM + ki * BK + c0k * 8;
        const __nv_bfloat16* gB = Bh + (size_t)(colBase + c0r) * KDIM + ki * BK + c0k * 8;
        CP_ASYNC16(ab + (c0r * PITCH + c0k * 8) * 2, gA);
        CP_ASYNC16(bb + (c0r * PITCH + c0k * 8) * 2, gB);
        const __nv_bfloat16* gA1 = Ah + (size_t)(rowBase + c1r) * KDIM + ki * BK + c1k * 8;
        const __nv_bfloat16* gB1 = Bh + (size_t)(colBase + c1r) * KDIM + ki * BK + c1k * 8;
        CP_ASYNC16(ab + (c1r * PITCH + c1k * 8) * 2, gA1);
        CP_ASYNC16(bb + (c1r * PITCH + c1k * 8) * 2, gB1);
    };

    load_tile(0, 0); CP_COMMIT();
    load_tile(1, 1); CP_COMMIT();

    const int aRowOff = (wy * 64 + (lane & 15)) * PITCH + (lane >> 4) * 8;
    const int bRowOff = (wx * 32 + (lane & 7) + ((lane >> 4) & 1) * 8) * PITCH
                      + ((lane >> 3) & 1) * 8;

    for (int ki = 0; ki < NITER; ++ki) {
        const int buf = ki & 1;
        if (ki < NITER - 1) { CP_WAIT1(); } else { CP_WAIT0(); }
        __syncthreads();
        const uint32_t ab = buf ? aBase1 : aBase0;
        const uint32_t bb = buf ? bBase1 : bBase0;

        #pragma unroll
        for (int s = 0; s < 2; ++s) {
            const int kk = s * 16;
            uint32_t a[4][4], b[4][2];
            #pragma unroll
            for (int mi = 0; mi < 4; ++mi)
                LDSM_X4(a[mi][0], a[mi][1], a[mi][2], a[mi][3],
                        ab + (aRowOff + mi * 16 * PITCH + kk) * 2);
            #pragma unroll
            for (int p = 0; p < 2; ++p) {
                uint32_t r0, r1, r2, r3;
                LDSM_X4(r0, r1, r2, r3, bb + (bRowOff + p * 16 * PITCH + kk) * 2);
                b[p * 2 + 0][0] = r0; b[p * 2 + 0][1] = r1;
                b[p * 2 + 1][0] = r2; b[p * 2 + 1][1] = r3;
            }
            #pragma unroll
            for (int mi = 0; mi < 4; ++mi)
                #pragma unroll
                for (int ni = 0; ni < 4; ++ni)
                    MMA16816(acc[mi][ni], a[mi], b[ni]);
        }
        __syncthreads();
        if (ki + 2 < NITER) { load_tile(buf, ki + 2); CP_COMMIT(); }
    }

    // epilogue: store logits + fused per-row rowmax
    const int colQ = colBase + wx * 32 + (lane & 3) * 2;
    #pragma unroll
    for (int mi = 0; mi < 4; ++mi) {
        const int r0 = rowBase + wy * 64 + mi * 16 + (lane >> 2);
        const int r1 = r0 + 8;
        float m0 = -__int_as_float(0x7F800000); int i0 = 0;
        float m1 = m0;                          int i1 = 0;
        #pragma unroll
        for (int ni = 0; ni < 4; ++ni) {
            const int col = colQ + ni * 8;
            float2 v0 = make_float2(acc[mi][ni][0], acc[mi][ni][1]);
            float2 v1 = make_float2(acc[mi][ni][2], acc[mi][ni][3]);
            *(float2*)(C + (size_t)r0 * NCB + col) = v0;
            *(float2*)(C + (size_t)r1 * NCB + col) = v1;
            if (v0.x > m0) { m0 = v0.x; i0 = col; }
            if (v0.y > m0) { m0 = v0.y; i0 = col + 1; }
            if (v1.x > m1) { m1 = v1.x; i1 = col; }
            if (v1.y > m1) { m1 = v1.y; i1 = col + 1; }
        }
        unsigned long long p0 = packmax(m0, i0);
        unsigned long long p1 = packmax(m1, i1);
        #pragma unroll
        for (int off = 1; off <= 2; off <<= 1) {
            unsigned long long o0 = __shfl_xor_sync(0xFFFFFFFFu, p0, off);
            unsigned long long o1 = __shfl_xor_sync(0xFFFFFFFFu, p1, off);
            if (o0 > p0) p0 = o0;
            if (o1 > p1) p1 = o1;
        }
        if ((lane & 3) == 0) {
            atomicMax(&best[r0], p0);
            atomicMax(&best[r1], p1);
        }
    }
}

// ---------------------------------------------------------------------------
// Refine: exact argmax among candidates, gather z_q, losses.
// ---------------------------------------------------------------------------
__global__ void refine(const float* __restrict__ C, float* __restrict__ out) {
    const int row = blockIdx.x;
    const int tid = threadIdx.x;
    __shared__ int   s_n;
    __shared__ int   s_col[128];
    __shared__ float s_dot[128];
    __shared__ int   s_win;
    __shared__ float s_wdot;

    unsigned long long p = g_best[row];
    float thr = mono2f((unsigned)(p >> 32)) - DELTA;
    if (tid == 0) s_n = 0;
    __syncthreads();

    const float* lr = C + (size_t)row * NCB;
    for (int j = tid; j < NCB; j += 256) {
        float v = lr[j];
        if (v >= thr) {
            int k = atomicAdd(&s_n, 1);
            if (k < 128) s_col[k] = j;
        }
    }
    __syncthreads();
    int n = min(s_n, 128);
    if (tid < n) {
        const float* a = g_xn + (size_t)row * DIM;
        const float* b = g_cb + (size_t)s_col[tid] * DIM;
        float acc = 0.0f;
        for (int k = 0; k < DIM; ++k)      // sequential fma: matched ref in R1
            acc = fmaf(a[k], b[k], acc);
        s_dot[tid] = acc;
    }
    __syncthreads();
    if (tid == 0) {
        float bd = -2.0f; int bc = 0x7FFFFFFF;
        for (int i = 0; i < n; ++i) {
            if (s_dot[i] > bd || (s_dot[i] == bd && s_col[i] < bc)) {
                bd = s_dot[i]; bc = s_col[i];
            }
        }
        s_win = bc; s_wdot = bd;
    }
    __syncthreads();
    const int idx = s_win;

    float4 v = ((const float4*)(g_cb + (size_t)idx * DIM))[tid];
    ((float4*)(out + OFF_ZQ   + (size_t)row * DIM))[tid] = v;
    ((float4*)(out + OFF_ZQST + (size_t)row * DIM))[tid] = v;

    if (tid == 0) {
        out[OFF_IDX + row] = (float)idx;
        double l = 1.0 - (double)s_wdot;
        atomicAdd(&g_commit_sum, l);
        if (idx >= NSEM) { atomicAdd(&g_vq_sum, l); atomicAdd(&g_vq_cnt, 1); }
    }
}

__global__ void finalize(float* __restrict__ out) {
    double commit = g_commit_sum / (double)NTOK;
    double vq     = g_vq_sum / ((double)g_vq_cnt + 1e-6);
    out[OFF_SC + 0] = (float)vq;
    out[OFF_SC + 1] = (float)commit;
    out[OFF_SC + 2] = (float)(vq + 0.25 * commit);
}

// ---------------------------------------------------------------------------
extern "C" void kernel_launch(void* const* d_in, const int* in_sizes, int n_in,
                              void* d_out, int out_size) {
    const float* x   = (const float*)d_in[0];
    const float* sem = (const float*)d_in[1];
    const float* lrn = (const float*)d_in[2];
    float* out = (float*)d_out;

    float *xn, *cb; __nv_bfloat16 *xh2, *ch2; unsigned long long* best;
    cudaGetSymbolAddress((void**)&xn, g_xn);
    cudaGetSymbolAddress((void**)&cb, g_cb);
    cudaGetSymbolAddress((void**)&xh2, g_xh2);
    cudaGetSymbolAddress((void**)&ch2, g_ch2);
    cudaGetSymbolAddress((void**)&best, g_best);

    init_state<<<32, 256>>>();
    // x:  A' = [hi | lo | hi]  -> hi at 0 and 2048, lo at 1024
    normalize_rows<<<NTOK, 256>>>(x, xn, xh2, 0, 2 * DIM, DIM);
    // cb: B' = [hi | hi | lo]  -> hi at 0 and 1024, lo at 2048
    normalize_rows<<<NSEM, 256>>>(sem, cb, ch2, 0, DIM, 2 * DIM);
    normalize_rows<<<NLRN, 256>>>(lrn, cb + (size_t)NSEM * DIM,
                                  ch2 + (size_t)NSEM * KDIM, 0, DIM, 2 * DIM);

    dim3 grid(NCB / BN, NTOK / BM);    // (65, 64)
    gemm_mma<<<grid, 256>>>(xh2, ch2, out + OFF_LOGITS, best);

    refine<<<NTOK, 256>>>(out + OFF_LOGITS, out);
    finalize<<<1, 1>>>(out);
}

// round 15
// speedup vs baseline: 1.9847x; 1.0574x over previous
#include <cuda_runtime.h>
#include <cuda_bf16.h>
#include <cstdint>

// ---------------------------------------------------------------------------
// HybridCodebook forward — tf32 HMMA single-pass (family-portable PTX;
// tcgen05 unavailable at compute_103 target).
//  logits  : tf32 m16n8k8 GEMM, fp32 accum. Measured bf16 logits err 2.35e-3
//            (R8) / 8 (3 extra mantissa bits) => ~2.9e-4 < 1e-3 threshold.
//  indices : approx rowmax in GEMM epilogue + exact fp32 candidate refinement
//  z_q etc : exact fp32
// Output layout (f32): [logits | indices | z_q | z_q_st | vq | commit | quant]
// ---------------------------------------------------------------------------

#define NTOK   8192
#define DIM    1024
#define NSEM   8192
#define NLRN   128
#define NCB    (NSEM + NLRN)     // 8320 = 65 * 128

#define BM     128
#define BN     128
#define BK     32
#define NITER  (DIM / BK)        // 32
#define PITCH  36                // floats per smem row (32 + 4 pad) = 144 B
#define TILEF  (BM * PITCH)      // 4608 floats per tile buffer
#define SMEM_BYTES (4 * TILEF * 4)   // A0,A1,B0,B1 = 73728 B
#define DELTA  1e-3f             // argmax candidate margin (~100 sigma tf32)

static const size_t OFF_LOGITS = 0;
static const size_t OFF_IDX    = (size_t)NTOK * NCB;
static const size_t OFF_ZQ     = OFF_IDX + NTOK;
static const size_t OFF_ZQST   = OFF_ZQ + (size_t)NTOK * DIM;
static const size_t OFF_SC     = OFF_ZQST + (size_t)NTOK * DIM;

// ---- device-global scratch (no allocations allowed) ----
__device__ float    g_xn[(size_t)NTOK * DIM];   // exact fp32 (refine)
__device__ float    g_cb[(size_t)NCB * DIM];    // exact fp32 (refine/gather)
__device__ uint32_t g_xt[(size_t)NTOK * DIM];   // tf32(xn) bit patterns
__device__ uint32_t g_ct[(size_t)NCB * DIM];    // tf32(cb) bit patterns
__device__ unsigned long long g_best[NTOK];     // (monofloat<<32) | (~col)
__device__ double g_commit_sum;
__device__ double g_vq_sum;
__device__ int    g_vq_cnt;

// ---------------------------------------------------------------------------
__device__ __forceinline__ uint32_t smem_u32(const void* p) {
    uint32_t a;
    asm("{ .reg .u64 t; cvta.to.shared.u64 t, %1; cvt.u32.u64 %0, t; }"
        : "=r"(a) : "l"(p));
    return a;
}
#define CP_ASYNC16(dst, src) \
    asm volatile("cp.async.cg.shared.global [%0], [%1], 16;" :: "r"(dst), "l"(src))
#define CP_COMMIT() asm volatile("cp.async.commit_group;" ::: "memory")
#define CP_WAIT1()  asm volatile("cp.async.wait_group 1;" ::: "memory")
#define CP_WAIT0()  asm volatile("cp.async.wait_group 0;" ::: "memory")

#define MMA1688(D, A, B) \
    asm volatile("mma.sync.aligned.m16n8k8.row.col.f32.tf32.tf32.f32 " \
                 "{%0,%1,%2,%3}, {%4,%5,%6,%7}, {%8,%9}, {%0,%1,%2,%3};" \
                 : "+f"((D)[0]), "+f"((D)[1]), "+f"((D)[2]), "+f"((D)[3]) \
                 : "r"((A)[0]), "r"((A)[1]), "r"((A)[2]), "r"((A)[3]), \
                   "r"((B)[0]), "r"((B)[1]))

__device__ __forceinline__ uint32_t f2tf32(float f) {
    uint32_t t;
    asm("cvt.rna.tf32.f32 %0, %1;" : "=r"(t) : "f"(f));
    return t;
}
__device__ __forceinline__ unsigned f2mono(float f) {
    unsigned u = __float_as_uint(f);
    return (u & 0x80000000u) ? ~u : (u | 0x80000000u);
}
__device__ __forceinline__ float mono2f(unsigned m) {
    return (m & 0x80000000u) ? __uint_as_float(m ^ 0x80000000u) : __uint_as_float(~m);
}
__device__ __forceinline__ unsigned long long packmax(float v, int col) {
    return ((unsigned long long)f2mono(v) << 32) | (0xFFFFFFFFu - (unsigned)col);
}

// ---------------------------------------------------------------------------
__global__ void init_state() {
    int i = blockIdx.x * blockDim.x + threadIdx.x;
    if (i < NTOK) g_best[i] = 0ull;
    if (i == 0) { g_commit_sum = 0.0; g_vq_sum = 0.0; g_vq_cnt = 0; }
}

// one block (256 threads) per row; fp32 out + tf32 out
__global__ void normalize_rows(const float* __restrict__ in,
                               float* __restrict__ outf,
                               uint32_t* __restrict__ outt) {
    const int row = blockIdx.x;
    const int tid = threadIdx.x;
    float4 v = ((const float4*)(in + (size_t)row * DIM))[tid];
    float s = v.x * v.x + v.y * v.y + v.z * v.z + v.w * v.w;
    #pragma unroll
    for (int off = 16; off; off >>= 1) s += __shfl_xor_sync(0xFFFFFFFFu, s, off);
    __shared__ float red[8];
    if ((tid & 31) == 0) red[tid >> 5] = s;
    __syncthreads();
    __shared__ float s_inv;
    if (tid == 0) {
        float t = red[0] + red[1] + red[2] + red[3] + red[4] + red[5] + red[6] + red[7];
        s_inv = 1.0f / fmaxf(sqrtf(t), 1e-8f);
    }
    __syncthreads();
    float inv = s_inv;
    float o[4] = {v.x * inv, v.y * inv, v.z * inv, v.w * inv};
    ((float4*)(outf + (size_t)row * DIM))[tid] = make_float4(o[0], o[1], o[2], o[3]);
    uint4 t;
    t.x = f2tf32(o[0]); t.y = f2tf32(o[1]); t.z = f2tf32(o[2]); t.w = f2tf32(o[3]);
    ((uint4*)(outt + (size_t)row * DIM))[tid] = t;
}

// ---------------------------------------------------------------------------
// tf32 GEMM: C[8192, 8320] = xt @ ct^T, fused per-row (max, argmax).
// 256 thr = 8 warps (2 M x 4 N), warp tile 64x32, mma m16n8k8, cp.async x2 buf.
// Scalar-LDS fragment loads; PITCH=36 floats => (4g+tg+c) mod 32 all distinct
// => conflict-free.
// ---------------------------------------------------------------------------
__global__ void __launch_bounds__(256, 2)
gemm_tf32(const uint32_t* __restrict__ At, const uint32_t* __restrict__ Bt,
          float* __restrict__ C, unsigned long long* __restrict__ best) {
    extern __shared__ __align__(16) uint32_t sm[];
    uint32_t* Abuf[2] = { sm,             sm + TILEF };
    uint32_t* Bbuf[2] = { sm + 2 * TILEF, sm + 3 * TILEF };

    const int tid  = threadIdx.x;
    const int lane = tid & 31;
    const int wid  = tid >> 5;
    const int wy   = wid >> 2;          // 0..1 (M)
    const int wx   = wid & 3;           // 0..3 (N)
    const int g    = lane >> 2;         // groupID 0..7
    const int tg   = lane & 3;          // threadID_in_group
    const int rowBase = blockIdx.y * BM;
    const int colBase = blockIdx.x * BN;

    // cp.async: tile = 128 rows x 32 floats (8 x 16B chunks/row); 2 thr/row, 4 chunks each
    const int ldRow = tid >> 1;
    const int ldOff = (tid & 1) * 16;   // float offset within row (0 or 16)

    const uint32_t aB0 = smem_u32(Abuf[0]), aB1 = smem_u32(Abuf[1]);
    const uint32_t bB0 = smem_u32(Bbuf[0]), bB1 = smem_u32(Bbuf[1]);

    float acc[4][4][4];
    #pragma unroll
    for (int mi = 0; mi < 4; ++mi)
        #pragma unroll
        for (int ni = 0; ni < 4; ++ni)
            #pragma unroll
            for (int q = 0; q < 4; ++q) acc[mi][ni][q] = 0.0f;

    auto load_tile = [&](int buf, int ki) {
        uint32_t ab = buf ? aB1 : aB0;
        uint32_t bb = buf ? bB1 : bB0;
        const uint32_t* gA = At + (size_t)(rowBase + ldRow) * DIM + ki * BK + ldOff;
        const uint32_t* gB = Bt + (size_t)(colBase + ldRow) * DIM + ki * BK + ldOff;
        const uint32_t da = ab + (ldRow * PITCH + ldOff) * 4;
        const uint32_t db = bb + (ldRow * PITCH + ldOff) * 4;
        #pragma unroll
        for (int j = 0; j < 4; ++j) {
            CP_ASYNC16(da + j * 16, gA + j * 4);
            CP_ASYNC16(db + j * 16, gB + j * 4);
        }
    };

    load_tile(0, 0); CP_COMMIT();
    load_tile(1, 1); CP_COMMIT();

    const int aBase = (wy * 64 + g) * PITCH + tg;    // + mi*16*PITCH + kk
    const int bBase = (wx * 32 + g) * PITCH + tg;    // + ni*8*PITCH  + kk

    for (int ki = 0; ki < NITER; ++ki) {
        const int buf = ki & 1;
        if (ki < NITER - 1) { CP_WAIT1(); } else { CP_WAIT0(); }
        __syncthreads();
        const uint32_t* sA = buf ? Abuf[1] : Abuf[0];
        const uint32_t* sB = buf ? Bbuf[1] : Bbuf[0];

        #pragma unroll
        for (int s = 0; s < 4; ++s) {              // four k8 steps in BK=32
            const int kk = s * 8;
            uint32_t a[4][4], b[4][2];
            #pragma unroll
            for (int mi = 0; mi < 4; ++mi) {
                const int o = aBase + mi * 16 * PITCH + kk;
                a[mi][0] = sA[o];
                a[mi][1] = sA[o + 8 * PITCH];
                a[mi][2] = sA[o + 4];
                a[mi][3] = sA[o + 8 * PITCH + 4];
            }
            #pragma unroll
            for (int ni = 0; ni < 4; ++ni) {
                const int o = bBase + ni * 8 * PITCH + kk;
                b[ni][0] = sB[o];
                b[ni][1] = sB[o + 4];
            }
            #pragma unroll
            for (int mi = 0; mi < 4; ++mi)
                #pragma unroll
                for (int ni = 0; ni < 4; ++ni)
                    MMA1688(acc[mi][ni], a[mi], b[ni]);
        }
        __syncthreads();
        if (ki + 2 < NITER) { load_tile(buf, ki + 2); CP_COMMIT(); }
    }

    // epilogue: store logits + fused per-row rowmax (C frag layout same as bf16)
    const int colQ = colBase + wx * 32 + tg * 2;
    #pragma unroll
    for (int mi = 0; mi < 4; ++mi) {
        const int r0 = rowBase + wy * 64 + mi * 16 + g;
        const int r1 = r0 + 8;
        float m0 = -__int_as_float(0x7F800000); int i0 = 0;
        float m1 = m0;                          int i1 = 0;
        #pragma unroll
        for (int ni = 0; ni < 4; ++ni) {
            const int col = colQ + ni * 8;
            float2 v0 = make_float2(acc[mi][ni][0], acc[mi][ni][1]);
            float2 v1 = make_float2(acc[mi][ni][2], acc[mi][ni][3]);
            *(float2*)(C + (size_t)r0 * NCB + col) = v0;
            *(float2*)(C + (size_t)r1 * NCB + col) = v1;
            if (v0.x > m0) { m0 = v0.x; i0 = col; }
            if (v0.y > m0) { m0 = v0.y; i0 = col + 1; }
            if (v1.x > m1) { m1 = v1.x; i1 = col; }
            if (v1.y > m1) { m1 = v1.y; i1 = col + 1; }
        }
        unsigned long long p0 = packmax(m0, i0);
        unsigned long long p1 = packmax(m1, i1);
        #pragma unroll
        for (int off = 1; off <= 2; off <<= 1) {   // reduce across quad (same row)
            unsigned long long o0 = __shfl_xor_sync(0xFFFFFFFFu, p0, off);
            unsigned long long o1 = __shfl_xor_sync(0xFFFFFFFFu, p1, off);
            if (o0 > p0) p0 = o0;
            if (o1 > p1) p1 = o1;
        }
        if (tg == 0) {
            atomicMax(&best[r0], p0);
            atomicMax(&best[r1], p1);
        }
    }
}

// ---------------------------------------------------------------------------
// Refine: exact argmax among candidates, gather z_q, losses.
// ---------------------------------------------------------------------------
__global__ void refine(const float* __restrict__ C, float* __restrict__ out) {
    const int row = blockIdx.x;
    const int tid = threadIdx.x;
    __shared__ int   s_n;
    __shared__ int   s_col[128];
    __shared__ float s_dot[128];
    __shared__ int   s_win;
    __shared__ float s_wdot;

    unsigned long long p = g_best[row];
    float thr = mono2f((unsigned)(p >> 32)) - DELTA;
    if (tid == 0) s_n = 0;
    __syncthreads();

    const float* lr = C + (size_t)row * NCB;
    for (int j = tid; j < NCB; j += 256) {
        float v = lr[j];
        if (v >= thr) {
            int k = atomicAdd(&s_n, 1);
            if (k < 128) s_col[k] = j;
        }
    }
    __syncthreads();
    int n = min(s_n, 128);
    if (tid < n) {
        const float* a = g_xn + (size_t)row * DIM;
        const float* b = g_cb + (size_t)s_col[tid] * DIM;
        float acc = 0.0f;
        for (int k = 0; k < DIM; ++k)      // sequential fma: matched ref in R1
            acc = fmaf(a[k], b[k], acc);
        s_dot[tid] = acc;
    }
    __syncthreads();
    if (tid == 0) {
        float bd = -2.0f; int bc = 0x7FFFFFFF;
        for (int i = 0; i < n; ++i) {
            if (s_dot[i] > bd || (s_dot[i] == bd && s_col[i] < bc)) {
                bd = s_dot[i]; bc = s_col[i];
            }
        }
        s_win = bc; s_wdot = bd;
    }
    __syncthreads();
    const int idx = s_win;

    float4 v = ((const float4*)(g_cb + (size_t)idx * DIM))[tid];
    ((float4*)(out + OFF_ZQ   + (size_t)row * DIM))[tid] = v;
    ((float4*)(out + OFF_ZQST + (size_t)row * DIM))[tid] = v;

    if (tid == 0) {
        out[OFF_IDX + row] = (float)idx;
        double l = 1.0 - (double)s_wdot;
        atomicAdd(&g_commit_sum, l);
        if (idx >= NSEM) { atomicAdd(&g_vq_sum, l); atomicAdd(&g_vq_cnt, 1); }
    }
}

__global__ void finalize(float* __restrict__ out) {
    double commit = g_commit_sum / (double)NTOK;
    double vq     = g_vq_sum / ((double)g_vq_cnt + 1e-6);
    out[OFF_SC + 0] = (float)vq;
    out[OFF_SC + 1] = (float)commit;
    out[OFF_SC + 2] = (float)(vq + 0.25 * commit);
}

// ---------------------------------------------------------------------------
extern "C" void kernel_launch(void* const* d_in, const int* in_sizes, int n_in,
                              void* d_out, int out_size) {
    const float* x   = (const float*)d_in[0];
    const float* sem = (const float*)d_in[1];
    const float* lrn = (const float*)d_in[2];
    float* out = (float*)d_out;

    float *xn, *cb; uint32_t *xt, *ct; unsigned long long* best;
    cudaGetSymbolAddress((void**)&xn, g_xn);
    cudaGetSymbolAddress((void**)&cb, g_cb);
    cudaGetSymbolAddress((void**)&xt, g_xt);
    cudaGetSymbolAddress((void**)&ct, g_ct);
    cudaGetSymbolAddress((void**)&best, g_best);

    cudaFuncSetAttribute(gemm_tf32, cudaFuncAttributeMaxDynamicSharedMemorySize,
                         SMEM_BYTES);

    init_state<<<32, 256>>>();
    normalize_rows<<<NTOK, 256>>>(x, xn, xt);
    normalize_rows<<<NSEM, 256>>>(sem, cb, ct);
    normalize_rows<<<NLRN, 256>>>(lrn, cb + (size_t)NSEM * DIM, ct + (size_t)NSEM * DIM);

    dim3 grid(NCB / BN, NTOK / BM);    // (65, 64)
    gemm_tf32<<<grid, 256, SMEM_BYTES>>>(xt, ct, out + OFF_LOGITS, best);

    refine<<<NTOK, 256>>>(out + OFF_LOGITS, out);
    finalize<<<1, 1>>>(out);
}